// round 11
// baseline (speedup 1.0000x reference)
#include <cuda_runtime.h>

#define THREADS 256
#define BLOCKS  1184   // 148 SMs * 8 blocks, one full wave at occ=8

// Self-cleaning global accumulator: last block publishes to out and resets
// state, so every graph replay sees identical initial conditions.
__device__ float        g_acc  = 0.0f;
__device__ unsigned int g_done = 0;

__global__ __launch_bounds__(THREADS, 8)
void loss_synonymy_kernel(const float4* __restrict__ s1,
                          const float4* __restrict__ s2,
                          const float*  __restrict__ score,
                          float* __restrict__ out,
                          int B)
{
    const int lane   = threadIdx.x & 31;
    const int warp   = (blockIdx.x * THREADS + threadIdx.x) >> 5;
    const int nwarps = (gridDim.x * THREADS) >> 5;

    // Contiguous-chunk-per-warp assignment: warp w streams ~B/nwarps
    // CONSECUTIVE rows, so its DRAM request stream is perfectly sequential
    // (successive 512B warp-requests hit the same/next DRAM page) instead of
    // jumping nwarps rows (~37MB) per iteration. Balanced split: first
    // `extra` warps take one additional row.
    const int rpw   = B / nwarps;            // rows per warp (floor)
    const int extra = B - rpw * nwarps;      // first `extra` warps get +1
    const int start = warp * rpw + (warp < extra ? warp : extra);
    const int count = rpw + (warp < extra ? 1 : 0);

    const float4* p1 = s1 + (long)start * 32 + lane;
    const float4* p2 = s2 + (long)start * 32 + lane;

    float acc = 0.0f;

    for (int i = 0; i < count; i++) {
        float4 a = __ldg(p1);
        float4 b = __ldg(p2);
        p1 += 32;              // next consecutive row (+2KB)
        p2 += 32;

        float dx = a.x - b.x;
        float dy = a.y - b.y;
        float dz = a.z - b.z;
        float dw = a.w - b.w;
        float ss = dx*dx + dy*dy + dz*dz + dw*dw;

        // warp all-reduce of sum of squares
        #pragma unroll
        for (int off = 16; off > 0; off >>= 1)
            ss += __shfl_xor_sync(0xffffffffu, ss, off);

        float t  = tanhf(sqrtf(ss));
        float sc = __ldg(&score[start + i]);  // uniform across warp
        float e  = (sc >= 0.6f) ? (1.0f - t) : (1.0f + t);
        acc += fmaxf(e, 0.0f);
    }

    // acc is lane-uniform after the all-reduce math; reduce warps in block.
    __shared__ float warp_sums[THREADS / 32];
    if (lane == 0) warp_sums[threadIdx.x >> 5] = acc;
    __syncthreads();

    if (threadIdx.x == 0) {
        float v = 0.0f;
        #pragma unroll
        for (int i = 0; i < THREADS / 32; i++) v += warp_sums[i];
        atomicAdd(&g_acc, v);
        __threadfence();
        unsigned int ticket = atomicAdd(&g_done, 1u);
        if (ticket == gridDim.x - 1) {
            out[0] = g_acc;   // publish
            g_acc  = 0.0f;    // reset for next replay
            g_done = 0;
        }
    }
}

extern "C" void kernel_launch(void* const* d_in, const int* in_sizes, int n_in,
                              void* d_out, int out_size)
{
    const float4* s1    = (const float4*)d_in[0];
    const float4* s2    = (const float4*)d_in[1];
    const float*  score = (const float*)d_in[2];
    float* out = (float*)d_out;

    const int B = in_sizes[2];  // synonymy_score has B elements

    loss_synonymy_kernel<<<BLOCKS, THREADS>>>(s1, s2, score, out, B);
}

// round 12
// speedup vs baseline: 1.0986x; 1.0986x over previous
#include <cuda_runtime.h>

#define THREADS 256
#define BLOCKS  1184   // 148 SMs * 8 blocks, one full wave, 64 warps/SM

// Self-cleaning global accumulator: last block publishes to out and resets
// state, so every graph replay sees identical initial conditions.
__device__ float        g_acc  = 0.0f;
__device__ unsigned int g_done = 0;

__global__ __launch_bounds__(THREADS, 8)
void loss_synonymy_kernel(const float4* __restrict__ s1,
                          const float4* __restrict__ s2,
                          const float*  __restrict__ score,
                          float* __restrict__ out,
                          int B)
{
    const int lane   = threadIdx.x & 31;
    const int warp   = (blockIdx.x * THREADS + threadIdx.x) >> 5;
    const int nwarps = (gridDim.x * THREADS) >> 5;

    // Warp-strided sweep (measured best: DRAM 90.3%, 7159 GB/s). At any
    // instant the chip's in-flight warps cover a dense ~19MB row window,
    // spreading load uniformly over all L2 slices and HBM channels.
    // Pointer-increment addressing; library tanhf (its FFMA chain
    // desynchronizes warps and smooths DRAM demand — measured faster than
    // MUFU tanh.approx, which caused L1tex queue bunching).
    const float4* p1 = s1 + (long)warp * 32 + lane;
    const float4* p2 = s2 + (long)warp * 32 + lane;
    const long    step = (long)nwarps * 32;

    float acc = 0.0f;

    for (int row = warp; row < B; row += nwarps) {
        float4 a = __ldg(p1);
        float4 b = __ldg(p2);
        float sc = __ldg(&score[row]);   // hoisted: overlaps the reduce chain
        p1 += step;
        p2 += step;

        float dx = a.x - b.x;
        float dy = a.y - b.y;
        float dz = a.z - b.z;
        float dw = a.w - b.w;
        float ss = dx*dx + dy*dy + dz*dz + dw*dw;

        // warp all-reduce of sum of squares
        #pragma unroll
        for (int off = 16; off > 0; off >>= 1)
            ss += __shfl_xor_sync(0xffffffffu, ss, off);

        float t = tanhf(sqrtf(ss));
        float e = (sc >= 0.6f) ? (1.0f - t) : (1.0f + t);
        acc += fmaxf(e, 0.0f);
    }

    // acc is lane-uniform after the all-reduce math; reduce warps in block.
    __shared__ float warp_sums[THREADS / 32];
    if (lane == 0) warp_sums[threadIdx.x >> 5] = acc;
    __syncthreads();

    if (threadIdx.x == 0) {
        float v = 0.0f;
        #pragma unroll
        for (int i = 0; i < THREADS / 32; i++) v += warp_sums[i];
        atomicAdd(&g_acc, v);
        __threadfence();
        unsigned int ticket = atomicAdd(&g_done, 1u);
        if (ticket == gridDim.x - 1) {
            out[0] = g_acc;   // publish
            g_acc  = 0.0f;    // reset for next replay
            g_done = 0;
        }
    }
}

extern "C" void kernel_launch(void* const* d_in, const int* in_sizes, int n_in,
                              void* d_out, int out_size)
{
    const float4* s1    = (const float4*)d_in[0];
    const float4* s2    = (const float4*)d_in[1];
    const float*  score = (const float*)d_in[2];
    float* out = (float*)d_out;

    const int B = in_sizes[2];  // synonymy_score has B elements

    loss_synonymy_kernel<<<BLOCKS, THREADS>>>(s1, s2, score, out, B);
}

// round 13
// speedup vs baseline: 1.1327x; 1.0310x over previous
#include <cuda_runtime.h>

#define THREADS 256
#define BLOCKS  1184   // 148 SMs * 8 blocks, one full wave, 64 warps/SM

// Self-cleaning global accumulator: last block publishes to out and resets
// state, so every graph replay sees identical initial conditions.
__device__ float        g_acc  = 0.0f;
__device__ unsigned int g_done = 0;

__global__ __launch_bounds__(THREADS, 8)
void loss_synonymy_kernel(const float4* __restrict__ s1,
                          const float4* __restrict__ s2,
                          const float*  __restrict__ score,
                          float* __restrict__ out,
                          int B)
{
    const int lane   = threadIdx.x & 31;
    const int warp   = (blockIdx.x * THREADS + threadIdx.x) >> 5;
    const int nwarps = (gridDim.x * THREADS) >> 5;

    // R8 body exactly (best measured: kernel 151.14us, DRAM 90.3%,
    // 7159 GB/s). Warp-strided sweep, pointer-increment addressing,
    // library tanhf, score load AFTER the reduce chain — measured best
    // placement; hoisting it regressed DRAM by 3.5% (R11).
    const float4* p1 = s1 + (long)warp * 32 + lane;
    const float4* p2 = s2 + (long)warp * 32 + lane;
    const long    step = (long)nwarps * 32;

    float acc = 0.0f;

    for (int row = warp; row < B; row += nwarps) {
        float4 a = __ldg(p1);
        float4 b = __ldg(p2);
        p1 += step;
        p2 += step;

        float dx = a.x - b.x;
        float dy = a.y - b.y;
        float dz = a.z - b.z;
        float dw = a.w - b.w;
        float ss = dx*dx + dy*dy + dz*dz + dw*dw;

        // warp all-reduce of sum of squares
        #pragma unroll
        for (int off = 16; off > 0; off >>= 1)
            ss += __shfl_xor_sync(0xffffffffu, ss, off);

        float t  = tanhf(sqrtf(ss));
        float sc = __ldg(&score[row]);  // uniform across warp
        float e  = (sc >= 0.6f) ? (1.0f - t) : (1.0f + t);
        acc += fmaxf(e, 0.0f);
    }

    // acc is lane-uniform after the all-reduce math; reduce warps in block.
    __shared__ float warp_sums[THREADS / 32];
    if (lane == 0) warp_sums[threadIdx.x >> 5] = acc;
    __syncthreads();

    if (threadIdx.x == 0) {
        float v = 0.0f;
        #pragma unroll
        for (int i = 0; i < THREADS / 32; i++) v += warp_sums[i];
        atomicAdd(&g_acc, v);
        __threadfence();
        unsigned int ticket = atomicAdd(&g_done, 1u);
        if (ticket == gridDim.x - 1) {
            out[0] = g_acc;   // publish
            g_acc  = 0.0f;    // reset for next replay
            g_done = 0;
        }
    }
}

extern "C" void kernel_launch(void* const* d_in, const int* in_sizes, int n_in,
                              void* d_out, int out_size)
{
    const float4* s1    = (const float4*)d_in[0];
    const float4* s2    = (const float4*)d_in[1];
    const float*  score = (const float*)d_in[2];
    float* out = (float*)d_out;

    const int B = in_sizes[2];  // synonymy_score has B elements

    loss_synonymy_kernel<<<BLOCKS, THREADS>>>(s1, s2, score, out, B);
}